// round 6
// baseline (speedup 1.0000x reference)
#include <cuda_runtime.h>
#include <cuda_bf16.h>

// AlphaRotatedIoULoss: loss = mean(1 - max(IoU_rot, 1e-6)^3) over N rotated-box pairs.
// Round 6: single fused kernel (threadfence reduction, self-resetting counter),
// coalesced smem-staged loads, trimmed branchless slab clip.

#define MAX_BLOCKS 16384
static __device__ float g_part[MAX_BLOCKS];
static __device__ unsigned int g_cnt = 0;   // self-resets via atomicInc wrap

// Clip edge (sx,sy)->(vx,vy) against slab -W <= x <= W.
// Emits two points: the clamped inside sub-segment, or (if the edge is entirely
// outside one side) both endpoints projected onto that boundary line. Collinear
// points on the clip line are shoelace-neutral, so no compaction is needed.
__device__ __forceinline__ void slab_edge(
    float sx, float sy, float vx, float vy, float W,
    float& ax, float& ay, float& bx, float& by)
{
    float dx = vx - sx;
    float dy = vy - sy;
    float adx = fabsf(dx);
    float dxs = (adx > 1e-12f) ? dx : copysignf(1e-12f, dx);
    float inv = __fdividef(1.0f, dxs);
    float tA = (-W - sx) * inv;
    float tB = ( W - sx) * inv;
    float tmin = fminf(tA, tB);
    float tmax = fmaxf(tA, tB);
    float t0 = fmaxf(tmin, 0.0f);
    float t1 = fminf(tmax, 1.0f);
    bool empty = (t0 > t1);              // both endpoints strictly outside, same side
    float pW = copysignf(W, sx);         // shared projected x for the empty case
    ax = empty ? pW : fmaf(t0, dx, sx);
    ay = empty ? sy : fmaf(t0, dy, sy);
    bx = empty ? pW : fmaf(t1, dx, sx);
    by = empty ? vy : fmaf(t1, dy, sy);
}

__global__ __launch_bounds__(256) void arl_fused_kernel(
    const float* __restrict__ pred,
    const float* __restrict__ tgt,
    float* __restrict__ out,
    int n, float inv_n)
{
    __shared__ float sp[1280];
    __shared__ float st[1280];
    __shared__ float wsum[8];
    __shared__ bool s_last;

    int tid  = threadIdx.x;
    int base = blockIdx.x * 256;
    int cnt  = n - base;                 // pairs handled by this block
    if (cnt > 256) cnt = 256;
    int fcount = cnt * 5;
    int fbase  = base * 5;

    // Coalesced staging: stride-256 loads hit full 128B sectors per warp.
    for (int j = tid; j < fcount; j += 256) {
        sp[j] = pred[fbase + j];
        st[j] = tgt[fbase + j];
    }
    __syncthreads();

    float loss = 0.0f;
    if (tid < cnt) {
        int o = tid * 5;   // stride 5 is coprime to 32 banks -> conflict-free
        float x1 = sp[o], y1 = sp[o + 1], w1 = sp[o + 2], h1 = sp[o + 3], a1 = sp[o + 4];
        float x2 = st[o], y2 = st[o + 1], w2 = st[o + 2], h2 = st[o + 3], a2 = st[o + 4];

        float s2f, c2f, s1f, c1f;
        __sincosf(a2, &s2f, &c2f);
        __sincosf(a1, &s1f, &c1f);

        // Box1 center in box2's local frame.
        float rx = x1 - x2, ry = y1 - y2;
        float lx =  rx * c2f + ry * s2f;
        float ly = -rx * s2f + ry * c2f;

        // Relative rotation.
        float c = c1f * c2f + s1f * s2f;
        float s = s1f * c2f - c1f * s2f;

        float hw1 = 0.5f * w1, hh1 = 0.5f * h1;
        float W = 0.5f * w2,  H = 0.5f * h2;

        float wx = hw1 * c, wy = hw1 * s;
        float hx = -hh1 * s, hy = hh1 * c;

        // Box1 corners (CCW) in box2 frame.
        float kx[4], ky[4];
        kx[0] = lx - wx - hx;  ky[0] = ly - wy - hy;
        kx[1] = lx + wx - hx;  ky[1] = ly + wy - hy;
        kx[2] = lx + wx + hx;  ky[2] = ly + wy + hy;
        kx[3] = lx - wx + hx;  ky[3] = ly - wy + hy;

        // Stage 1: clip against |x| <= W. 4 edges -> 8 points (static indexing).
        float Px[8], Py[8];
        #pragma unroll
        for (int e = 0; e < 4; e++) {
            int e1 = (e + 1) & 3;
            slab_edge(kx[e], ky[e], kx[e1], ky[e1], W,
                      Px[2 * e], Py[2 * e], Px[2 * e + 1], Py[2 * e + 1]);
        }

        // Stage 2: clip against |y| <= H with fused shoelace accumulation.
        float acc = 0.0f;
        float a0x = 0.0f, a0y = 0.0f;
        float pbx = 0.0f, pby = 0.0f;
        #pragma unroll
        for (int e = 0; e < 8; e++) {
            int e1 = (e + 1) & 7;
            float ax, ay, bx, by;
            slab_edge(Py[e], Px[e], Py[e1], Px[e1], H, ay, ax, by, bx);
            if (e == 0) { a0x = ax; a0y = ay; }
            else        { acc += pbx * ay - ax * pby; }
            acc += ax * by - bx * ay;
            pbx = bx; pby = by;
        }
        acc += pbx * a0y - a0x * pby;

        float inter = 0.5f * fabsf(acc);
        float area1 = w1 * h1;
        float area2 = w2 * h2;
        float iou = __fdividef(inter, area1 + area2 - inter);
        iou = fmaxf(iou, 1e-6f);
        loss = 1.0f - iou * iou * iou;
    }

    // Block reduction.
    #pragma unroll
    for (int off = 16; off > 0; off >>= 1)
        loss += __shfl_down_sync(0xffffffffu, loss, off);
    int lane = tid & 31;
    int wid  = tid >> 5;
    if (lane == 0) wsum[wid] = loss;
    __syncthreads();
    if (wid == 0) {
        float v = (lane < 8) ? wsum[lane] : 0.0f;
        #pragma unroll
        for (int off = 4; off > 0; off >>= 1)
            v += __shfl_down_sync(0xffu, v, off);
        if (lane == 0) {
            g_part[blockIdx.x] = v;
            __threadfence();
            // atomicInc wraps to 0 after gridDim.x increments -> counter is 0
            // again at the end of every launch (graph-replay deterministic).
            unsigned int old = atomicInc(&g_cnt, gridDim.x - 1);
            s_last = (old == gridDim.x - 1);
        }
    }
    __syncthreads();

    // Last block reduces all per-block partials and writes the mean.
    if (s_last) {
        double v = 0.0;
        for (int j = tid; j < gridDim.x; j += 256)
            v += (double)g_part[j];
        #pragma unroll
        for (int off = 16; off > 0; off >>= 1)
            v += __shfl_down_sync(0xffffffffu, v, off);
        __shared__ double dsum[8];
        if (lane == 0) dsum[wid] = v;
        __syncthreads();
        if (wid == 0) {
            double d = (lane < 8) ? dsum[lane] : 0.0;
            #pragma unroll
            for (int off = 4; off > 0; off >>= 1)
                d += __shfl_down_sync(0xffu, d, off);
            if (lane == 0)
                out[0] = (float)(d * (double)inv_n);
        }
    }
}

extern "C" void kernel_launch(void* const* d_in, const int* in_sizes, int n_in,
                              void* d_out, int out_size)
{
    const float* pred = (const float*)d_in[0];
    const float* tgt  = (const float*)d_in[1];
    float* out = (float*)d_out;
    int n = in_sizes[0] / 5;

    int blocks = (n + 255) / 256;
    if (blocks > MAX_BLOCKS) blocks = MAX_BLOCKS;   // N=1e6 -> 3907, well within
    arl_fused_kernel<<<blocks, 256>>>(pred, tgt, out, n, 1.0f / (float)n);
}

// round 8
// speedup vs baseline: 1.1750x; 1.1750x over previous
#include <cuda_runtime.h>
#include <cuda_bf16.h>

// AlphaRotatedIoULoss: loss = mean(1 - max(IoU_rot, 1e-6)^3) over N rotated-box pairs.
// Round 7: single fused kernel (threadfence reduction, self-resetting counter)
// with DIRECT ldg loads (round-6 smem staging regressed: barrier-serialized the
// memory phase and added ALU/LDS tax; LDG latency was already occupancy-hidden).
// Stage-1 slope inverses exploit the box's central symmetry (2 fewer RCPs).

#define MAX_BLOCKS 16384
static __device__ float g_part[MAX_BLOCKS];
static __device__ unsigned int g_cnt = 0;   // wraps back to 0 every launch

__device__ __forceinline__ float safe_inv(float dx) {
    float dxs = (fabsf(dx) > 1e-12f) ? dx : copysignf(1e-12f, dx);
    return __fdividef(1.0f, dxs);
}

// Clip edge (sx,sy)->(vx,vy) against slab -W <= x <= W; inv = 1/dx (clamped).
// Emits two points: the clamped inside sub-segment, or (if fully outside one
// side) both endpoints projected onto that boundary line. Collinear points on
// the clip line are shoelace-neutral, so no compaction is needed.
__device__ __forceinline__ void slab_edge(
    float sx, float sy, float vx, float vy, float inv, float W,
    float& ax, float& ay, float& bx, float& by)
{
    float dx = vx - sx;
    float dy = vy - sy;
    float tA = (-W - sx) * inv;
    float tB = ( W - sx) * inv;
    float tmin = fminf(tA, tB);
    float tmax = fmaxf(tA, tB);
    float t0 = fmaxf(tmin, 0.0f);
    float t1 = fminf(tmax, 1.0f);
    bool empty = (t0 > t1);              // edge entirely outside, one side
    float pW = copysignf(W, sx);         // shared projected x for the empty case
    ax = empty ? pW : fmaf(t0, dx, sx);
    ay = empty ? sy : fmaf(t0, dy, sy);
    bx = empty ? pW : fmaf(t1, dx, sx);
    by = empty ? vy : fmaf(t1, dy, sy);
}

__global__ __launch_bounds__(256) void arl_fused_kernel(
    const float* __restrict__ pred,
    const float* __restrict__ tgt,
    float* __restrict__ out,
    int n, float inv_n)
{
    int tid = threadIdx.x;
    int i = blockIdx.x * 256 + tid;
    float loss = 0.0f;

    if (i < n) {
        const float* p = pred + 5 * i;
        const float* t = tgt + 5 * i;
        float x1 = __ldg(p + 0), y1 = __ldg(p + 1), w1 = __ldg(p + 2),
              h1 = __ldg(p + 3), a1 = __ldg(p + 4);
        float x2 = __ldg(t + 0), y2 = __ldg(t + 1), w2 = __ldg(t + 2),
              h2 = __ldg(t + 3), a2 = __ldg(t + 4);

        float s2f, c2f, s1f, c1f;
        __sincosf(a2, &s2f, &c2f);
        __sincosf(a1, &s1f, &c1f);

        // Box1 center in box2's local frame.
        float rx = x1 - x2, ry = y1 - y2;
        float lx =  rx * c2f + ry * s2f;
        float ly = -rx * s2f + ry * c2f;

        // Relative rotation.
        float c = c1f * c2f + s1f * s2f;
        float s = s1f * c2f - c1f * s2f;

        float hw1 = 0.5f * w1, hh1 = 0.5f * h1;
        float W = 0.5f * w2,  H = 0.5f * h2;

        float wx = hw1 * c, wy = hw1 * s;
        float hx = -hh1 * s, hy = hh1 * c;

        // Box1 corners (CCW) in box2 frame.
        float kx[4], ky[4];
        kx[0] = lx - wx - hx;  ky[0] = ly - wy - hy;
        kx[1] = lx + wx - hx;  ky[1] = ly + wy - hy;
        kx[2] = lx + wx + hx;  ky[2] = ly + wy + hy;
        kx[3] = lx - wx + hx;  ky[3] = ly - wy + hy;

        // Stage 1: clip against |x| <= W. Central symmetry: edge2 = -edge0,
        // edge3 = -edge1, and the epsilon clamp is antisymmetric, so the slope
        // inverses negate exactly. 2 RCPs instead of 4.
        float inv01 = safe_inv(kx[1] - kx[0]);
        float inv12 = safe_inv(kx[2] - kx[1]);
        float einv[4] = { inv01, inv12, -inv01, -inv12 };

        float Px[8], Py[8];
        #pragma unroll
        for (int e = 0; e < 4; e++) {
            int e1 = (e + 1) & 3;
            slab_edge(kx[e], ky[e], kx[e1], ky[e1], einv[e], W,
                      Px[2 * e], Py[2 * e], Px[2 * e + 1], Py[2 * e + 1]);
        }

        // Stage 2: clip against |y| <= H with fused shoelace accumulation.
        float acc = 0.0f;
        float a0x = 0.0f, a0y = 0.0f;
        float pbx = 0.0f, pby = 0.0f;
        #pragma unroll
        for (int e = 0; e < 8; e++) {
            int e1 = (e + 1) & 7;
            float ax, ay, bx, by;
            float iv = safe_inv(Py[e1] - Py[e]);
            slab_edge(Py[e], Px[e], Py[e1], Px[e1], iv, H, ay, ax, by, bx);
            if (e == 0) { a0x = ax; a0y = ay; }
            else        { acc += pbx * ay - ax * pby; }
            acc += ax * by - bx * ay;
            pbx = bx; pby = by;
        }
        acc += pbx * a0y - a0x * pby;

        float inter = 0.5f * fabsf(acc);
        float area1 = w1 * h1;
        float area2 = w2 * h2;
        float iou = __fdividef(inter, area1 + area2 - inter);
        iou = fmaxf(iou, 1e-6f);
        loss = 1.0f - iou * iou * iou;
    }

    // Block reduction.
    __shared__ float wsum[8];
    __shared__ bool s_last;
    #pragma unroll
    for (int off = 16; off > 0; off >>= 1)
        loss += __shfl_down_sync(0xffffffffu, loss, off);
    int lane = tid & 31;
    int wid  = tid >> 5;
    if (lane == 0) wsum[wid] = loss;
    __syncthreads();
    if (wid == 0) {
        float v = (lane < 8) ? wsum[lane] : 0.0f;
        #pragma unroll
        for (int off = 4; off > 0; off >>= 1)
            v += __shfl_down_sync(0xffu, v, off);
        if (lane == 0) {
            g_part[blockIdx.x] = v;
            __threadfence();
            // atomicInc wraps to 0 after gridDim.x increments -> counter ends
            // every launch at 0 (graph-replay deterministic).
            unsigned int old = atomicInc(&g_cnt, gridDim.x - 1);
            s_last = (old == gridDim.x - 1);
        }
    }
    __syncthreads();

    // Last block reduces the per-block partials and writes the mean.
    if (s_last) {
        double v = 0.0;
        for (int j = tid; j < gridDim.x; j += 256)
            v += (double)g_part[j];
        #pragma unroll
        for (int off = 16; off > 0; off >>= 1)
            v += __shfl_down_sync(0xffffffffu, v, off);
        __shared__ double dsum[8];
        if (lane == 0) dsum[wid] = v;
        __syncthreads();
        if (wid == 0) {
            double d = (lane < 8) ? dsum[lane] : 0.0;
            #pragma unroll
            for (int off = 4; off > 0; off >>= 1)
                d += __shfl_down_sync(0xffu, d, off);
            if (lane == 0)
                out[0] = (float)(d * (double)inv_n);
        }
    }
}

extern "C" void kernel_launch(void* const* d_in, const int* in_sizes, int n_in,
                              void* d_out, int out_size)
{
    const float* pred = (const float*)d_in[0];
    const float* tgt  = (const float*)d_in[1];
    float* out = (float*)d_out;
    int n = in_sizes[0] / 5;

    int blocks = (n + 255) / 256;
    if (blocks > MAX_BLOCKS) blocks = MAX_BLOCKS;   // N=1e6 -> 3907, fits
    arl_fused_kernel<<<blocks, 256>>>(pred, tgt, out, n, 1.0f / (float)n);
}